// round 1
// baseline (speedup 1.0000x reference)
#include <cuda_runtime.h>

#define B_    128
#define T_    25
#define L_    49
#define V_    10000
#define E_    512
#define H_    512
#define ENC_  512
#define KIN_  1536   // E + ENC + H

// ---- scratch (device globals; no allocation allowed) ----
__device__ float g_enc_proj[B_ * L_ * H_];   // 12.8 MB
__device__ float g_hp[B_ * H_];
__device__ float g_ctx[B_ * ENC_];
__device__ float g_h[2][B_ * H_];
__device__ float g_c[2][B_ * H_];

// ---- packed fp32x2 helpers (sm_103a) ----
__device__ __forceinline__ unsigned long long ld64s(const float* p) {
    return *reinterpret_cast<const unsigned long long*>(p);
}
__device__ __forceinline__ void fma2(unsigned long long& d,
                                     unsigned long long a,
                                     unsigned long long b) {
    asm("fma.rn.f32x2 %0, %1, %2, %0;" : "+l"(d) : "l"(a), "l"(b));
}
__device__ __forceinline__ float sum2(unsigned long long v) {
    return __uint_as_float((unsigned)(v & 0xffffffffull)) +
           __uint_as_float((unsigned)(v >> 32));
}

// ---------------------------------------------------------------------------
// Generic Y[M,N] = X[M,K] @ W[N,K]^T (+bias), tiles 32(m) x 64(n), Kc=32.
// 256 threads, each computes 2m x 4n with packed f32x2 FMAs.
// Requires M % 32 == 0, K % 32 == 0. N guarded.
// ---------------------------------------------------------------------------
__global__ void gemm_xwt(const float* __restrict__ X, const float* __restrict__ W,
                         const float* __restrict__ bias, float* __restrict__ Y,
                         int M, int N, int K, int ldy) {
    __shared__ float Xs[32][34];
    __shared__ float Ws[64][34];
    const int tid = threadIdx.x;
    const int tx = tid & 15, ty = tid >> 4;
    const int nbase = blockIdx.x * 64;
    const int mbase = blockIdx.y * 32;

    unsigned long long acc[2][4];
#pragma unroll
    for (int j = 0; j < 2; j++)
#pragma unroll
        for (int i = 0; i < 4; i++) acc[j][i] = 0ull;

    for (int kb = 0; kb < K; kb += 32) {
#pragma unroll
        for (int q = 0; q < 4; q++) {
            int idx = tid + q * 256;
            int r = idx >> 5, c = idx & 31;
            Xs[r][c] = X[(mbase + r) * K + kb + c];
        }
#pragma unroll
        for (int q = 0; q < 8; q++) {
            int idx = tid + q * 256;
            int r = idx >> 5, c = idx & 31;
            int n = nbase + r;
            Ws[r][c] = (n < N) ? W[n * K + kb + c] : 0.0f;
        }
        __syncthreads();
#pragma unroll
        for (int kk = 0; kk < 32; kk += 2) {
            unsigned long long xv0 = ld64s(&Xs[ty][kk]);
            unsigned long long xv1 = ld64s(&Xs[ty + 16][kk]);
#pragma unroll
            for (int i = 0; i < 4; i++) {
                unsigned long long wv = ld64s(&Ws[tx + 16 * i][kk]);
                fma2(acc[0][i], xv0, wv);
                fma2(acc[1][i], xv1, wv);
            }
        }
        __syncthreads();
    }

#pragma unroll
    for (int j = 0; j < 2; j++) {
        int m = mbase + ty + 16 * j;
#pragma unroll
        for (int i = 0; i < 4; i++) {
            int n = nbase + tx + 16 * i;
            if (n < N) {
                float y = sum2(acc[j][i]);
                if (bias) y += bias[n];
                Y[m * ldy + n] = y;
            }
        }
    }
}

// ---------------------------------------------------------------------------
// Attention: per-b block. scores[l] = sum_h tanh(hp[h]+enc_proj[b,l,h])*v[h];
// softmax over L; context[e] = sum_l attn[l]*enc[b,l,e].
// ---------------------------------------------------------------------------
__global__ void attn_kernel(const float* __restrict__ enc,
                            const float* __restrict__ vattn) {
    const int b = blockIdx.x;
    const int tid = threadIdx.x;
    const int wid = tid >> 5, lane = tid & 31;

    __shared__ float hp_s[H_];
    __shared__ float v_s[H_];
    __shared__ float sc[L_];
    __shared__ float red[8];
    __shared__ float red2[8];

    for (int j = tid; j < H_; j += 256) {
        hp_s[j] = g_hp[b * H_ + j];
        v_s[j] = vattn[j];
    }
    __syncthreads();

    const float* ep = g_enc_proj + b * L_ * H_;
    for (int l = wid; l < L_; l += 8) {
        float p = 0.f;
        for (int k = lane; k < H_; k += 32)
            p += tanhf(hp_s[k] + ep[l * H_ + k]) * v_s[k];
#pragma unroll
        for (int o = 16; o; o >>= 1) p += __shfl_xor_sync(0xffffffffu, p, o);
        if (lane == 0) sc[l] = p;
    }
    __syncthreads();

    // softmax over L_=49
    float val = (tid < L_) ? sc[tid] : -3.4e38f;
    float m = val;
#pragma unroll
    for (int o = 16; o; o >>= 1) m = fmaxf(m, __shfl_xor_sync(0xffffffffu, m, o));
    if (lane == 0) red[wid] = m;
    __syncthreads();
    if (tid == 0) {
        float mm = red[0];
        for (int w = 1; w < 8; w++) mm = fmaxf(mm, red[w]);
        red[0] = mm;
    }
    __syncthreads();
    m = red[0];
    float e = (tid < L_) ? expf(val - m) : 0.f;
    float s = e;
#pragma unroll
    for (int o = 16; o; o >>= 1) s += __shfl_xor_sync(0xffffffffu, s, o);
    if (lane == 0) red2[wid] = s;
    __syncthreads();
    if (tid == 0) {
        float ss = 0.f;
        for (int w = 0; w < 8; w++) ss += red2[w];
        red2[0] = 1.0f / ss;
    }
    __syncthreads();
    if (tid < L_) sc[tid] = e * red2[0];
    __syncthreads();

    // context
    const float* eb = enc + b * L_ * ENC_;
#pragma unroll
    for (int q = 0; q < 2; q++) {
        int ecol = tid + q * 256;
        float a = 0.f;
        for (int l = 0; l < L_; l++) a += sc[l] * eb[l * ENC_ + ecol];
        g_ctx[b * ENC_ + ecol] = a;
    }
}

// ---------------------------------------------------------------------------
// Fused LSTM gates GEMM + pointwise update.
// Virtual X[b, 0:1536] = [emb(cap[b,t]) | ctx[b] | h_in[b]],
// virtual W[2048,1536] = [W_ih | W_hh], gate rows g*512+j.
// Block: 32 b x 16 j (x4 gates). 256 threads, thread = 2b x (1j x 4 gates).
// ---------------------------------------------------------------------------
__global__ void lstm_kernel(const int* __restrict__ captions, int t,
                            const float* __restrict__ emb,
                            const float* __restrict__ W_ih,
                            const float* __restrict__ W_hh,
                            const float* __restrict__ b_ih,
                            const float* __restrict__ b_hh,
                            const float* __restrict__ h_in,
                            float* __restrict__ h_out,
                            const float* __restrict__ c_in,
                            float* __restrict__ c_out) {
    __shared__ float Xs[32][34];
    __shared__ float Ws[64][34];
    __shared__ int cap_s[32];

    const int tid = threadIdx.x;
    const int tx = tid & 15, ty = tid >> 4;
    const int jbase = blockIdx.x * 16;
    const int bbase = blockIdx.y * 32;

    if (tid < 32) cap_s[tid] = captions[(bbase + tid) * T_ + t];
    __syncthreads();

    unsigned long long acc[2][4];
#pragma unroll
    for (int p = 0; p < 2; p++)
#pragma unroll
        for (int g = 0; g < 4; g++) acc[p][g] = 0ull;

    for (int kb = 0; kb < KIN_; kb += 32) {
#pragma unroll
        for (int q = 0; q < 4; q++) {
            int idx = tid + q * 256;
            int r = idx >> 5, c = idx & 31;
            int k = kb + c;
            int b = bbase + r;
            float v;
            if (k < 512)        v = emb[cap_s[r] * E_ + k];
            else if (k < 1024)  v = g_ctx[b * ENC_ + (k - 512)];
            else                v = h_in[b * H_ + (k - 1024)];
            Xs[r][c] = v;
        }
#pragma unroll
        for (int q = 0; q < 8; q++) {
            int idx = tid + q * 256;
            int r = idx >> 5, c = idx & 31;
            int k = kb + c;
            int row = (r >> 4) * 512 + jbase + (r & 15);
            Ws[r][c] = (k < 1024) ? W_ih[row * 1024 + k]
                                  : W_hh[row * 512 + (k - 1024)];
        }
        __syncthreads();
#pragma unroll
        for (int kk = 0; kk < 32; kk += 2) {
            unsigned long long xv0 = ld64s(&Xs[ty][kk]);
            unsigned long long xv1 = ld64s(&Xs[ty + 16][kk]);
#pragma unroll
            for (int g = 0; g < 4; g++) {
                unsigned long long wv = ld64s(&Ws[g * 16 + tx][kk]);
                fma2(acc[0][g], xv0, wv);
                fma2(acc[1][g], xv1, wv);
            }
        }
        __syncthreads();
    }

    const int j = jbase + tx;
    float bias[4];
#pragma unroll
    for (int g = 0; g < 4; g++) {
        int row = g * 512 + j;
        bias[g] = b_ih[row] + b_hh[row];
    }
#pragma unroll
    for (int p = 0; p < 2; p++) {
        int b = bbase + ty + 16 * p;
        float gi = sum2(acc[p][0]) + bias[0];
        float gf = sum2(acc[p][1]) + bias[1];
        float gg = sum2(acc[p][2]) + bias[2];
        float go = sum2(acc[p][3]) + bias[3];
        float si = 1.f / (1.f + expf(-gi));
        float sf = 1.f / (1.f + expf(-gf));
        float so = 1.f / (1.f + expf(-go));
        float cn = sf * c_in[b * H_ + j] + si * tanhf(gg);
        c_out[b * H_ + j] = cn;
        h_out[b * H_ + j] = so * tanhf(cn);
    }
}

__global__ void zero_state() {
    int i = blockIdx.x * 256 + threadIdx.x;
    g_h[0][i] = 0.f;
    g_c[0][i] = 0.f;
}

// ---------------------------------------------------------------------------
extern "C" void kernel_launch(void* const* d_in, const int* in_sizes, int n_in,
                              void* d_out, int out_size) {
    const int*   captions = (const int*)d_in[0];
    const float* enc      = (const float*)d_in[1];
    const float* emb      = (const float*)d_in[2];
    const float* W_h      = (const float*)d_in[3];
    const float* W_e      = (const float*)d_in[4];
    const float* v_attn   = (const float*)d_in[5];
    const float* W_ih     = (const float*)d_in[6];
    const float* W_hh     = (const float*)d_in[7];
    const float* b_ih     = (const float*)d_in[8];
    const float* b_hh     = (const float*)d_in[9];
    const float* W_fc     = (const float*)d_in[10];
    const float* b_fc     = (const float*)d_in[11];
    float* out = (float*)d_out;

    float *ep, *hp, *hbuf, *cbuf;
    cudaGetSymbolAddress((void**)&ep,   g_enc_proj);
    cudaGetSymbolAddress((void**)&hp,   g_hp);
    cudaGetSymbolAddress((void**)&hbuf, g_h);
    cudaGetSymbolAddress((void**)&cbuf, g_c);

    zero_state<<<(B_ * H_) / 256, 256>>>();

    // loop-invariant encoder projection: [B*L, H] = enc[B*L, ENC] @ W_e^T
    {
        dim3 grid((H_ + 63) / 64, (B_ * L_) / 32);
        gemm_xwt<<<grid, 256>>>(enc, W_e, nullptr, ep, B_ * L_, H_, ENC_, H_);
    }

    for (int t = 0; t < T_; t++) {
        const float* hin  = hbuf + (t & 1) * B_ * H_;
        float*       hout = hbuf + ((t + 1) & 1) * B_ * H_;
        const float* cin  = cbuf + (t & 1) * B_ * H_;
        float*       cout = cbuf + ((t + 1) & 1) * B_ * H_;

        // hidden projection: hp = h @ W_h^T
        {
            dim3 grid(H_ / 64, B_ / 32);
            gemm_xwt<<<grid, 256>>>(hin, W_h, nullptr, hp, B_, H_, H_, H_);
        }
        // attention -> g_ctx
        attn_kernel<<<B_, 256>>>(enc, v_attn);
        // LSTM gates + state update
        {
            dim3 grid(H_ / 16, B_ / 32);
            lstm_kernel<<<grid, 256>>>(captions, t, emb, W_ih, W_hh,
                                       b_ih, b_hh, hin, hout, cin, cout);
        }
        // logits = h_new @ W_fc^T + b_fc  -> out[:, t, :]
        {
            dim3 grid((V_ + 63) / 64, B_ / 32);
            gemm_xwt<<<grid, 256>>>(hout, W_fc, b_fc, out + t * V_,
                                    B_, V_, H_, T_ * V_);
        }
    }
}

// round 2
// speedup vs baseline: 2.8794x; 2.8794x over previous
#include <cuda_runtime.h>

#define B_    128
#define T_    25
#define L_    49
#define V_    10000
#define E_    512
#define H_    512
#define ENC_  512
#define BL_   (B_ * L_)      // 6272
#define BT_   (B_ * T_)      // 3200
#define VPAD_ 10048

typedef unsigned long long ull;

// ---------------- device scratch (globals; zero-init at load) ----------------
__device__ float g_encT[ENC_ * BL_];          // [512][6272]
__device__ float g_enc_proj[BL_ * H_];        // [6272][512]
__device__ float g_embT[E_ * BT_];            // [512][3200]
__device__ float g_gates_pre[BT_ * 4 * H_];   // [3200][2048] (incl. biases)
__device__ float g_WfcT[H_ * VPAD_];          // [512][10048], cols >=10000 stay 0
__device__ float g_WgT[(E_ + ENC_ + H_) * 4 * H_]; // [1536][2048] = [W_ih^T ; W_hh^T]
__device__ float g_WhT[H_ * H_];
__device__ float g_WeT[ENC_ * H_];
__device__ float g_bsum[4 * H_];
__device__ float g_hp4[4 * B_ * H_];          // 4 K-splits of hidden proj
__device__ float g_ctxT[ENC_ * B_];           // [512][128]
__device__ float g_hT[(T_ + 1) * H_ * B_];    // 26 slots of [512][128]
__device__ float g_c[2 * B_ * H_];
__device__ float g_gates2[2 * B_ * 4 * H_];   // 2 K-splits of gates

// ---------------- fast transcendentals (ex2/rcp approx) ----------------
__device__ __forceinline__ float fex2(float x) {
    float y; asm("ex2.approx.ftz.f32 %0, %1;" : "=f"(y) : "f"(x)); return y;
}
__device__ __forceinline__ float frcp(float x) {
    float y; asm("rcp.approx.ftz.f32 %0, %1;" : "=f"(y) : "f"(x)); return y;
}
__device__ __forceinline__ float ftanh(float x) {
    float xc = fminf(fmaxf(x, -8.f), 8.f);
    float e = fex2(xc * 2.8853900817779268f);   // e^{2x}
    return (e - 1.f) * frcp(e + 1.f);
}
__device__ __forceinline__ float fsig(float x) {
    float xc = fminf(fmaxf(x, -30.f), 30.f);
    float e = fex2(-xc * 1.4426950408889634f);
    return frcp(1.f + e);
}

// ---------------- f32x2 helpers ----------------
__device__ __forceinline__ void fma2(ull& d, ull a, ull b) {
    asm("fma.rn.f32x2 %0, %1, %2, %0;" : "+l"(d) : "l"(a), "l"(b));
}
__device__ __forceinline__ ull pack2(float x) {
    ull r; asm("mov.b64 %0, {%1, %1};" : "=l"(r) : "f"(x)); return r;
}
__device__ __forceinline__ float lo2(ull v) { return __uint_as_float((unsigned)v); }
__device__ __forceinline__ float hi2(ull v) { return __uint_as_float((unsigned)(v >> 32)); }

struct XP { const float* p[4]; };

// ---------------------------------------------------------------------------
// GEMM: Y[m, n] = sum_k XT[k][m] * WT[k][n]  (+bias), M-tile fixed 128.
// XT: k-major, column stride mstride. WT: k-major, row stride nstride.
// grid.x: N tiles of NTILE; grid.y: M/128; grid.z: K splits of KLEN.
// Thread tile: 8m x NT4 n, m packed into f32x2 accumulators.
// ---------------------------------------------------------------------------
template<int NTILE>
__global__ void __launch_bounds__(256) gemm_t(
    XP xp, int mstride, const float* __restrict__ WT, int nstride,
    const float* __restrict__ bias, float* __restrict__ Y,
    long ldy, long ysplit, int N, int KLEN)
{
    constexpr int NT4 = NTILE / 16;
    __shared__ float Xs[16][128];
    __shared__ float Ws[16][NTILE];
    const int tid = threadIdx.x;
    const int tx = tid & 15, ty = tid >> 4;
    const int nb = blockIdx.x * NTILE;
    const int z = blockIdx.z;
    const float* XT = xp.p[z] + blockIdx.y * 128;
    const float* Wz = WT + (size_t)z * KLEN * nstride;
    float* Yz = Y + (size_t)z * ysplit + (size_t)blockIdx.y * 128 * ldy;

    ull acc[4][NT4];
#pragma unroll
    for (int i = 0; i < 4; i++)
#pragma unroll
        for (int j = 0; j < NT4; j++) acc[i][j] = 0ull;

    for (int k0 = 0; k0 < KLEN; k0 += 16) {
#pragma unroll
        for (int q = 0; q < 2; q++) {
            int idx = tid + q * 256;
            int k = idx >> 5, mw = (idx & 31) << 2;
            *(float4*)&Xs[k][mw] =
                *(const float4*)(XT + (size_t)(k0 + k) * mstride + mw);
        }
        if (NTILE == 64) {
            int k = tid >> 4, nw = (tid & 15) << 2;
            *(float4*)&Ws[k][nw] =
                *(const float4*)(Wz + (size_t)(k0 + k) * nstride + nb + nw);
        } else {
            if (tid < 128) {
                int k = tid >> 3, nw = (tid & 7) << 2;
                *(float4*)&Ws[k][nw] =
                    *(const float4*)(Wz + (size_t)(k0 + k) * nstride + nb + nw);
            }
        }
        __syncthreads();
#pragma unroll
        for (int kk = 0; kk < 16; kk++) {
            ull a0 = *(const ull*)&Xs[kk][ty * 8 + 0];
            ull a1 = *(const ull*)&Xs[kk][ty * 8 + 2];
            ull a2 = *(const ull*)&Xs[kk][ty * 8 + 4];
            ull a3 = *(const ull*)&Xs[kk][ty * 8 + 6];
            float bf[NT4];
            if (NT4 == 4) {
                float4 t4 = *(const float4*)&Ws[kk][tx * 4];
                bf[0] = t4.x; bf[1] = t4.y; bf[2] = t4.z; bf[3] = t4.w;
            } else {
                float2 t2 = *(const float2*)&Ws[kk][tx * 2];
                bf[0] = t2.x; bf[1] = t2.y;
            }
#pragma unroll
            for (int j = 0; j < NT4; j++) {
                ull bb = pack2(bf[j]);
                fma2(acc[0][j], a0, bb);
                fma2(acc[1][j], a1, bb);
                fma2(acc[2][j], a2, bb);
                fma2(acc[3][j], a3, bb);
            }
        }
        __syncthreads();
    }

    float bv[NT4];
#pragma unroll
    for (int j = 0; j < NT4; j++) {
        int n = nb + tx * NT4 + j;
        bv[j] = (bias != nullptr && n < N) ? bias[n] : 0.f;
    }
#pragma unroll
    for (int i = 0; i < 4; i++) {
        int m = ty * 8 + i * 2;
#pragma unroll
        for (int j = 0; j < NT4; j++) {
            int n = nb + tx * NT4 + j;
            if (n < N) {
                Yz[(size_t)m * ldy + n]       = lo2(acc[i][j]) + bv[j];
                Yz[(size_t)(m + 1) * ldy + n] = hi2(acc[i][j]) + bv[j];
            }
        }
    }
}

// ---------------------------------------------------------------------------
// 32x32 tiled transpose: out[c*ostride + r] = in[r*C + c]
// ---------------------------------------------------------------------------
__global__ void transp(const float* __restrict__ in, float* __restrict__ out,
                       int R, int C, int ostride) {
    __shared__ float t[32][33];
    int c0 = blockIdx.x * 32, r0 = blockIdx.y * 32;
#pragma unroll
    for (int i = threadIdx.y; i < 32; i += 8) {
        int r = r0 + i, c = c0 + threadIdx.x;
        t[i][threadIdx.x] = (r < R && c < C) ? in[(size_t)r * C + c] : 0.f;
    }
    __syncthreads();
#pragma unroll
    for (int i = threadIdx.y; i < 32; i += 8) {
        int c = c0 + i, r = r0 + threadIdx.x;
        if (c < C && r < R) out[(size_t)c * ostride + r] = t[threadIdx.x][i];
    }
}

__global__ void bias_sum(const float* __restrict__ bi,
                         const float* __restrict__ bh) {
    int i = blockIdx.x * 256 + threadIdx.x;
    g_bsum[i] = bi[i] + bh[i];
}

__global__ void emb_gather(const int* __restrict__ cap,
                           const float* __restrict__ emb) {
    int m = blockIdx.x;            // m = t*128 + b
    int b = m & 127, t = m >> 7;
    int w = cap[b * T_ + t];
    const float* row = emb + (size_t)w * E_;
    for (int k = threadIdx.x; k < E_; k += blockDim.x)
        g_embT[(size_t)k * BT_ + m] = row[k];
}

__global__ void zero_state() {
    int i = blockIdx.x * 256 + threadIdx.x;   // 65536 threads
    g_hT[i] = 0.f;       // slot 0
    g_c[i]  = 0.f;       // parity 0
}

// ---------------------------------------------------------------------------
// Attention (one block per batch row, 512 threads):
//   hp = sum of 4 K-splits; scores l = sum_h tanh(hp+ep)*v; softmax; context.
// Writes ctxT[e][b].
// ---------------------------------------------------------------------------
__global__ void __launch_bounds__(512) attn_kernel(
    const float* __restrict__ enc, const float* __restrict__ vattn) {
    const int b = blockIdx.x, tid = threadIdx.x;
    __shared__ float hp_s[H_];
    __shared__ float v_s[H_];
    __shared__ float sc[64];

    hp_s[tid] = g_hp4[0 * B_ * H_ + b * H_ + tid]
              + g_hp4[1 * B_ * H_ + b * H_ + tid]
              + g_hp4[2 * B_ * H_ + b * H_ + tid]
              + g_hp4[3 * B_ * H_ + b * H_ + tid];
    v_s[tid] = vattn[tid];
    __syncthreads();

    const int w = tid >> 5, lane = tid & 31;
    const float* ep = g_enc_proj + (size_t)b * L_ * H_;
    for (int l = w; l < L_; l += 16) {
        const float* row = ep + l * H_;
        float p = 0.f;
#pragma unroll
        for (int k = lane; k < H_; k += 32)
            p += ftanh(hp_s[k] + row[k]) * v_s[k];
#pragma unroll
        for (int o = 16; o; o >>= 1) p += __shfl_xor_sync(0xffffffffu, p, o);
        if (lane == 0) sc[l] = p;
    }
    __syncthreads();

    if (tid < 32) {
        float v0 = sc[tid];
        float v1 = (tid < L_ - 32) ? sc[32 + tid] : -1e30f;
        float mx = fmaxf(v0, v1);
#pragma unroll
        for (int o = 16; o; o >>= 1) mx = fmaxf(mx, __shfl_xor_sync(0xffffffffu, mx, o));
        float e0 = fex2((v0 - mx) * 1.4426950408889634f);
        float e1 = (tid < L_ - 32) ? fex2((v1 - mx) * 1.4426950408889634f) : 0.f;
        float s = e0 + e1;
#pragma unroll
        for (int o = 16; o; o >>= 1) s += __shfl_xor_sync(0xffffffffu, s, o);
        float r = frcp(s);
        sc[tid] = e0 * r;
        if (tid < L_ - 32) sc[32 + tid] = e1 * r;
    }
    __syncthreads();

    const float* eb = enc + (size_t)b * L_ * ENC_;
    float a = 0.f;
#pragma unroll 7
    for (int l = 0; l < L_; l++) a += sc[l] * eb[l * ENC_ + tid];
    g_ctxT[(size_t)tid * B_ + b] = a;
}

// ---------------------------------------------------------------------------
// LSTM pointwise: gates = split0 + split1 + precomputed emb-gates(+bias);
// writes c[t+1 parity] and hT slot t+1.
// ---------------------------------------------------------------------------
__global__ void __launch_bounds__(512) lstm_pw(int t) {
    const int b = blockIdx.x, j = threadIdx.x;
    const float* gp = g_gates_pre + ((size_t)(t * B_ + b)) * (4 * H_);
    const float* g0 = g_gates2 + (size_t)b * (4 * H_);
    const float* g1 = g_gates2 + (size_t)B_ * (4 * H_) + (size_t)b * (4 * H_);
    float gi = g0[j]            + g1[j]            + gp[j];
    float gf = g0[H_ + j]       + g1[H_ + j]       + gp[H_ + j];
    float gg = g0[2 * H_ + j]   + g1[2 * H_ + j]   + gp[2 * H_ + j];
    float go = g0[3 * H_ + j]   + g1[3 * H_ + j]   + gp[3 * H_ + j];

    const float* cin = g_c + (size_t)(t & 1) * B_ * H_ + (size_t)b * H_;
    float* cout = g_c + (size_t)((t + 1) & 1) * B_ * H_ + (size_t)b * H_;
    float cn = fsig(gf) * cin[j] + fsig(gi) * ftanh(gg);
    cout[j] = cn;
    float h = fsig(go) * ftanh(cn);
    g_hT[(size_t)(t + 1) * H_ * B_ + (size_t)j * B_ + b] = h;
}

// ---------------------------------------------------------------------------
extern "C" void kernel_launch(void* const* d_in, const int* in_sizes, int n_in,
                              void* d_out, int out_size) {
    const int*   captions = (const int*)d_in[0];
    const float* enc      = (const float*)d_in[1];
    const float* emb      = (const float*)d_in[2];
    const float* W_h      = (const float*)d_in[3];
    const float* W_e      = (const float*)d_in[4];
    const float* v_attn   = (const float*)d_in[5];
    const float* W_ih     = (const float*)d_in[6];
    const float* W_hh     = (const float*)d_in[7];
    const float* b_ih     = (const float*)d_in[8];
    const float* b_hh     = (const float*)d_in[9];
    const float* W_fc     = (const float*)d_in[10];
    const float* b_fc     = (const float*)d_in[11];
    float* out = (float*)d_out;

    static cudaStream_t s2 = nullptr;
    static cudaEvent_t evL = nullptr, evJ = nullptr;
    if (!s2) {
        cudaStreamCreateWithFlags(&s2, cudaStreamNonBlocking);
        cudaEventCreateWithFlags(&evL, cudaEventDisableTiming);
        cudaEventCreateWithFlags(&evJ, cudaEventDisableTiming);
    }

    float *encT, *enc_proj, *embT, *gates_pre, *WfcT, *WgT, *WhT, *WeT,
          *bsum, *hp4, *ctxT, *hT, *gates2;
    cudaGetSymbolAddress((void**)&encT,      g_encT);
    cudaGetSymbolAddress((void**)&enc_proj,  g_enc_proj);
    cudaGetSymbolAddress((void**)&embT,      g_embT);
    cudaGetSymbolAddress((void**)&gates_pre, g_gates_pre);
    cudaGetSymbolAddress((void**)&WfcT,      g_WfcT);
    cudaGetSymbolAddress((void**)&WgT,       g_WgT);
    cudaGetSymbolAddress((void**)&WhT,       g_WhT);
    cudaGetSymbolAddress((void**)&WeT,       g_WeT);
    cudaGetSymbolAddress((void**)&bsum,      g_bsum);
    cudaGetSymbolAddress((void**)&hp4,       g_hp4);
    cudaGetSymbolAddress((void**)&ctxT,      g_ctxT);
    cudaGetSymbolAddress((void**)&hT,        g_hT);
    cudaGetSymbolAddress((void**)&gates2,    g_gates2);

    const dim3 tb(32, 8);

    zero_state<<<256, 256>>>();
    transp<<<dim3(16, 16),  tb>>>(W_h,  WhT, H_, H_, H_);
    transp<<<dim3(16, 16),  tb>>>(W_e,  WeT, H_, ENC_, H_);
    transp<<<dim3(16, 313), tb>>>(W_fc, WfcT, V_, H_, VPAD_);
    transp<<<dim3(32, 64),  tb>>>(W_ih, WgT, 4 * H_, E_ + ENC_, 4 * H_);
    transp<<<dim3(16, 64),  tb>>>(W_hh, WgT + (size_t)(E_ + ENC_) * 4 * H_,
                                  4 * H_, H_, 4 * H_);
    transp<<<dim3(16, 196), tb>>>(enc, encT, BL_, ENC_, BL_);
    bias_sum<<<8, 256>>>(b_ih, b_hh);
    emb_gather<<<BT_, 128>>>(captions, emb);

    {   // gates_pre[3200][2048] = embX @ W_ih[:, :512]^T + (b_ih+b_hh)
        XP x{{embT, embT, embT, embT}};
        gemm_t<64><<<dim3(32, T_, 1), 256>>>(x, BT_, WgT, 4 * H_, bsum,
                                             gates_pre, 4L * H_, 0L, 4 * H_, E_);
    }
    {   // enc_proj[6272][512] = enc @ W_e^T
        XP x{{encT, encT, encT, encT}};
        gemm_t<64><<<dim3(8, BL_ / 128, 1), 256>>>(x, BL_, WeT, H_, nullptr,
                                                   enc_proj, (long)H_, 0L, H_, ENC_);
    }

    for (int t = 0; t < T_; t++) {
        const float* hTt = hT + (size_t)t * H_ * B_;
        {   // hidden proj, 4-way split-K
            XP x{{hTt, hTt + 128 * B_, hTt + 256 * B_, hTt + 384 * B_}};
            gemm_t<32><<<dim3(16, 1, 4), 256>>>(x, B_, WhT, H_, nullptr,
                                                hp4, (long)H_, (long)(B_ * H_),
                                                H_, 128);
        }
        attn_kernel<<<B_, 512>>>(enc, v_attn);
        {   // gates (ctx | h), 2-way split-K over [W_ih[:,512:] ; W_hh]
            XP x{{ctxT, hTt, ctxT, ctxT}};
            gemm_t<32><<<dim3(64, 1, 2), 256>>>(x, B_,
                                                WgT + (size_t)E_ * 4 * H_, 4 * H_,
                                                nullptr, gates2, 4L * H_,
                                                (long)(B_ * 4 * H_), 4 * H_, H_);
        }
        lstm_pw<<<B_, 512>>>(t);
        cudaEventRecord(evL, 0);
        cudaStreamWaitEvent(s2, evL, 0);
        {   // logits on stream 2, overlapped with next step's chain
            XP x{{hTt + H_ * B_, hTt + H_ * B_, hTt + H_ * B_, hTt + H_ * B_}};
            gemm_t<64><<<dim3(157, 1, 1), 256, 0, s2>>>(
                x, B_, WfcT, VPAD_, b_fc, out + (size_t)t * V_,
                (long)(T_ * V_), 0L, V_, H_);
        }
    }
    cudaEventRecord(evJ, s2);
    cudaStreamWaitEvent(0, evJ, 0);
}

// round 5
// speedup vs baseline: 2.9170x; 1.0131x over previous
#include <cuda_runtime.h>
#include <cuda_bf16.h>
#include <cstdint>

#define B_    128
#define T_    25
#define L_    49
#define V_    10000
#define E_    512
#define H_    512
#define ENC_  512
#define BL_   (B_ * L_)      // 6272
#define BT_   (B_ * T_)      // 3200
#define KBIG_ 1536
#define VPAD_ 10112          // 79 * 128

typedef unsigned long long ull;

// ---------------- device scratch ----------------
__device__ float g_enc_proj[BL_ * H_];
__device__ float g_gates_pre[BT_ * 4 * H_];
__device__ float g_WgT2[1024 * 4 * H_];     // [k 0..1023][2048]: [Wih cols 512.. ; Whh]
__device__ float g_WhT[H_ * H_];
__device__ float g_bsum[4 * H_];
__device__ float g_hp4[4 * B_ * H_];
__device__ float g_ctxT[ENC_ * B_];
__device__ float g_hT[(T_ + 1) * H_ * B_];
__device__ float g_c[2 * B_ * H_];
__device__ float g_gates2[2 * B_ * 4 * H_];
// bf16 split operands (A: hi|hi|lo, B: hi|lo|hi)
__device__ __align__(16) __nv_bfloat16 g_Wbig[(size_t)VPAD_ * KBIG_];
__device__ __align__(16) __nv_bfloat16 g_hbig[(size_t)T_ * B_ * KBIG_];
__device__ __align__(16) __nv_bfloat16 g_encA[(size_t)BL_ * KBIG_];
__device__ __align__(16) __nv_bfloat16 g_embX[(size_t)BT_ * KBIG_];
__device__ __align__(16) __nv_bfloat16 g_WeB[(size_t)H_ * KBIG_];
__device__ __align__(16) __nv_bfloat16 g_WihB[(size_t)(4 * H_) * KBIG_];

// ---------------- fast transcendentals ----------------
__device__ __forceinline__ float fex2(float x) {
    float y; asm("ex2.approx.ftz.f32 %0, %1;" : "=f"(y) : "f"(x)); return y;
}
__device__ __forceinline__ float frcp(float x) {
    float y; asm("rcp.approx.ftz.f32 %0, %1;" : "=f"(y) : "f"(x)); return y;
}
__device__ __forceinline__ float ftanh(float x) {
    float xc = fminf(fmaxf(x, -8.f), 8.f);
    float e = fex2(xc * 2.8853900817779268f);
    return (e - 1.f) * frcp(e + 1.f);
}
__device__ __forceinline__ float fsig(float x) {
    float xc = fminf(fmaxf(x, -30.f), 30.f);
    float e = fex2(-xc * 1.4426950408889634f);
    return frcp(1.f + e);
}

// ---------------- f32x2 helpers ----------------
__device__ __forceinline__ void fma2(ull& d, ull a, ull b) {
    asm("fma.rn.f32x2 %0, %1, %2, %0;" : "+l"(d) : "l"(a), "l"(b));
}
__device__ __forceinline__ ull pack2(float x) {
    ull r; asm("mov.b64 %0, {%1, %1};" : "=l"(r) : "f"(x)); return r;
}
__device__ __forceinline__ float lo2(ull v) { return __uint_as_float((unsigned)v); }
__device__ __forceinline__ float hi2(ull v) { return __uint_as_float((unsigned)(v >> 32)); }

struct XP { const float* p[4]; };

// ---------------- mma.sync helpers ----------------
__device__ __forceinline__ uint32_t smem_u32(const void* p) {
    uint32_t a;
    asm("{ .reg .u64 t; cvta.to.shared.u64 t, %1; cvt.u32.u64 %0, t; }"
        : "=r"(a) : "l"(p));
    return a;
}
__device__ __forceinline__ void ldm_x4(uint32_t* r, uint32_t addr) {
    asm volatile("ldmatrix.sync.aligned.m8n8.x4.shared.b16 {%0,%1,%2,%3}, [%4];"
        : "=r"(r[0]), "=r"(r[1]), "=r"(r[2]), "=r"(r[3]) : "r"(addr));
}
__device__ __forceinline__ void mma_bf16(float* d, const uint32_t* a,
                                         uint32_t b0, uint32_t b1) {
    asm volatile("mma.sync.aligned.m16n8k16.row.col.f32.bf16.bf16.f32 "
        "{%0,%1,%2,%3}, {%4,%5,%6,%7}, {%8,%9}, {%0,%1,%2,%3};"
        : "+f"(d[0]), "+f"(d[1]), "+f"(d[2]), "+f"(d[3])
        : "r"(a[0]), "r"(a[1]), "r"(a[2]), "r"(a[3]), "r"(b0), "r"(b1));
}

// ---------------------------------------------------------------------------
// bf16-split HMMA GEMM: out[m,n] = sum_k A[m,k]*Bm[n,k] (+bias), K fixed 1536.
// A: [M][1536] bf16 (hi|hi|lo); Bm: [N][1536] bf16 (hi|lo|hi).
// CTA tile 128x128, 8 warps (2m x 4n), warp tile 64x32.
// ---------------------------------------------------------------------------
__global__ void __launch_bounds__(256) mma_gemm(
    const __nv_bfloat16* __restrict__ A,
    const __nv_bfloat16* __restrict__ Bm,
    const float* __restrict__ bias,
    float* __restrict__ out, long ldout, int Nvalid)
{
    __shared__ __align__(16) __nv_bfloat16 smt[2][2][128][40];  // pitch 80B
    const int tid = threadIdx.x;
    const int l = tid & 31, wid = tid >> 5;
    const int wm = wid >> 2, wn = wid & 3;
    const int mbase = blockIdx.y * 128;
    const int nbase = blockIdx.x * 128;
    const __nv_bfloat16* Asrc = A + (size_t)mbase * KBIG_;
    const __nv_bfloat16* Bsrc = Bm + (size_t)nbase * KBIG_;

    float d[4][4][4];
#pragma unroll
    for (int i = 0; i < 4; i++)
#pragma unroll
        for (int j = 0; j < 4; j++)
#pragma unroll
            for (int q = 0; q < 4; q++) d[i][j][q] = 0.f;

    const uint32_t sb = smem_u32(smt);
    const int arow = wm * 64 + (l & 15);
    const int acol = (l >> 4) * 8;
    const int brow = wn * 32 + ((l >> 4) << 3) + (l & 7);
    const int bcol = ((l >> 3) & 1) * 8;

    auto ldglobal = [&](int c, int buf) {
#pragma unroll
        for (int q = 0; q < 4; q++) {
            int idx = tid + q * 256;
            int half = idx >> 9;
            int r = (idx >> 2) & 127;
            int cq = idx & 3;
            const __nv_bfloat16* s = half ? Bsrc : Asrc;
            uint4 v = *(const uint4*)(s + (size_t)r * KBIG_ + c * 32 + cq * 8);
            *(uint4*)(&smt[buf][half][r][cq * 8]) = v;
        }
    };

    ldglobal(0, 0);
    __syncthreads();
#pragma unroll 1
    for (int c = 0; c < 48; c++) {
        const int buf = c & 1;
        if (c + 1 < 48) ldglobal(c + 1, buf ^ 1);
        const uint32_t base = sb + buf * 20480;
#pragma unroll
        for (int s = 0; s < 2; s++) {
            uint32_t ar[4][4];
#pragma unroll
            for (int fm = 0; fm < 4; fm++)
                ldm_x4(ar[fm],
                       base + ((arow + fm * 16) * 40 + acol + s * 16) * 2);
#pragma unroll
            for (int fp = 0; fp < 2; fp++) {
                uint32_t br[4];
                ldm_x4(br, base + 10240 +
                           ((brow + fp * 16) * 40 + bcol + s * 16) * 2);
#pragma unroll
                for (int fm = 0; fm < 4; fm++) {
                    mma_bf16(d[fm][fp * 2],     ar[fm], br[0], br[1]);
                    mma_bf16(d[fm][fp * 2 + 1], ar[fm], br[2], br[3]);
                }
            }
        }
        __syncthreads();
    }

#pragma unroll
    for (int fm = 0; fm < 4; fm++) {
        int m0 = mbase + wm * 64 + fm * 16 + (l >> 2);
#pragma unroll
        for (int fn = 0; fn < 4; fn++) {
            int n0 = nbase + wn * 32 + fn * 8 + (l & 3) * 2;
            if (n0 < Nvalid) {
                float b0 = bias ? bias[n0] : 0.f;
                float b1 = bias ? bias[n0 + 1] : 0.f;
                float2 v0 = make_float2(d[fm][fn][0] + b0, d[fm][fn][1] + b1);
                float2 v1 = make_float2(d[fm][fn][2] + b0, d[fm][fn][3] + b1);
                *(float2*)&out[(size_t)m0 * ldout + n0] = v0;
                *(float2*)&out[(size_t)(m0 + 8) * ldout + n0] = v1;
            }
        }
    }
}

// ---------------------------------------------------------------------------
// fp32x2 GEMM (k-major operands) — proven R2 kernel
// ---------------------------------------------------------------------------
template<int NTILE>
__global__ void __launch_bounds__(256) gemm_t(
    XP xp, int mstride, const float* __restrict__ WT, int nstride,
    const float* __restrict__ bias, float* __restrict__ Y,
    long ldy, long ysplit, int N, int KLEN)
{
    constexpr int NT4 = NTILE / 16;
    __shared__ float Xs[16][128];
    __shared__ float Ws[16][NTILE];
    const int tid = threadIdx.x;
    const int tx = tid & 15, ty = tid >> 4;
    const int nb = blockIdx.x * NTILE;
    const int z = blockIdx.z;
    const float* XT = xp.p[z] + blockIdx.y * 128;
    const float* Wz = WT + (size_t)z * KLEN * nstride;
    float* Yz = Y + (size_t)z * ysplit + (size_t)blockIdx.y * 128 * ldy;

    ull acc[4][NT4];
#pragma unroll
    for (int i = 0; i < 4; i++)
#pragma unroll
        for (int j = 0; j < NT4; j++) acc[i][j] = 0ull;

    for (int k0 = 0; k0 < KLEN; k0 += 16) {
#pragma unroll
        for (int q = 0; q < 2; q++) {
            int idx = tid + q * 256;
            int k = idx >> 5, mw = (idx & 31) << 2;
            *(float4*)&Xs[k][mw] =
                *(const float4*)(XT + (size_t)(k0 + k) * mstride + mw);
        }
        if (NTILE == 64) {
            int k = tid >> 4, nw = (tid & 15) << 2;
            *(float4*)&Ws[k][nw] =
                *(const float4*)(Wz + (size_t)(k0 + k) * nstride + nb + nw);
        } else {
            if (tid < 128) {
                int k = tid >> 3, nw = (tid & 7) << 2;
                *(float4*)&Ws[k][nw] =
                    *(const float4*)(Wz + (size_t)(k0 + k) * nstride + nb + nw);
            }
        }
        __syncthreads();
#pragma unroll
        for (int kk = 0; kk < 16; kk++) {
            ull a0 = *(const ull*)&Xs[kk][ty * 8 + 0];
            ull a1 = *(const ull*)&Xs[kk][ty * 8 + 2];
            ull a2 = *(const ull*)&Xs[kk][ty * 8 + 4];
            ull a3 = *(const ull*)&Xs[kk][ty * 8 + 6];
            float bf[NT4];
            if (NT4 == 4) {
                float4 t4 = *(const float4*)&Ws[kk][tx * 4];
                bf[0] = t4.x; bf[1] = t4.y; bf[2] = t4.z; bf[3] = t4.w;
            } else {
                float2 t2 = *(const float2*)&Ws[kk][tx * 2];
                bf[0] = t2.x; bf[1] = t2.y;
            }
#pragma unroll
            for (int j = 0; j < NT4; j++) {
                ull bb = pack2(bf[j]);
                fma2(acc[0][j], a0, bb);
                fma2(acc[1][j], a1, bb);
                fma2(acc[2][j], a2, bb);
                fma2(acc[3][j], a3, bb);
            }
        }
        __syncthreads();
    }

    float bv[NT4];
#pragma unroll
    for (int j = 0; j < NT4; j++) {
        int n = nb + tx * NT4 + j;
        bv[j] = (bias != nullptr && n < N) ? bias[n] : 0.f;
    }
#pragma unroll
    for (int i = 0; i < 4; i++) {
        int m = ty * 8 + i * 2;
#pragma unroll
        for (int j = 0; j < NT4; j++) {
            int n = nb + tx * NT4 + j;
            if (n < N) {
                Yz[(size_t)m * ldy + n]       = lo2(acc[i][j]) + bv[j];
                Yz[(size_t)(m + 1) * ldy + n] = hi2(acc[i][j]) + bv[j];
            }
        }
    }
}

// ---------------------------------------------------------------------------
__global__ void transp(const float* __restrict__ in, float* __restrict__ out,
                       int R, int C, int istride, int ostride) {
    __shared__ float t[32][33];
    int c0 = blockIdx.x * 32, r0 = blockIdx.y * 32;
#pragma unroll
    for (int i = threadIdx.y; i < 32; i += 8) {
        int r = r0 + i, c = c0 + threadIdx.x;
        t[i][threadIdx.x] = (r < R && c < C) ? in[(size_t)r * istride + c] : 0.f;
    }
    __syncthreads();
#pragma unroll
    for (int i = threadIdx.y; i < 32; i += 8) {
        int c = c0 + i, r = r0 + threadIdx.x;
        if (c < C && r < R) out[(size_t)c * ostride + r] = t[threadIdx.x][i];
    }
}

__global__ void bias_sum(const float* __restrict__ bi, const float* __restrict__ bh) {
    int i = blockIdx.x * 256 + threadIdx.x;
    g_bsum[i] = bi[i] + bh[i];
}

// B-split: row n -> (hi | lo | hi)
__global__ void bsplit(const float* __restrict__ src, int ldsrc,
                       __nv_bfloat16* __restrict__ dst, int Nsrc) {
    int n = blockIdx.x, j = threadIdx.x;
    float w = (n < Nsrc) ? src[(size_t)n * ldsrc + j] : 0.f;
    __nv_bfloat16 hi = __float2bfloat16(w);
    float lo = w - __bfloat162float(hi);
    __nv_bfloat16* row = dst + (size_t)n * KBIG_;
    row[j] = hi;
    row[512 + j] = __float2bfloat16(lo);
    row[1024 + j] = hi;
}

// A-split: row m -> (hi | hi | lo)
__global__ void asplit(const float* __restrict__ src, __nv_bfloat16* __restrict__ dst) {
    int m = blockIdx.x, j = threadIdx.x;
    float v = src[(size_t)m * 512 + j];
    __nv_bfloat16 hi = __float2bfloat16(v);
    float lo = v - __bfloat162float(hi);
    __nv_bfloat16* row = dst + (size_t)m * KBIG_;
    row[j] = hi;
    row[512 + j] = hi;
    row[1024 + j] = __float2bfloat16(lo);
}

// embedding gather + A-split into g_embX rows (m = t*128 + b)
__global__ void emb_gather(const int* __restrict__ cap, const float* __restrict__ emb) {
    int m = blockIdx.x;
    int b = m & 127, t = m >> 7;
    int w = cap[b * T_ + t];
    int j = threadIdx.x;
    float v = emb[(size_t)w * E_ + j];
    __nv_bfloat16 hi = __float2bfloat16(v);
    float lo = v - __bfloat162float(hi);
    __nv_bfloat16* row = g_embX + (size_t)m * KBIG_;
    row[j] = hi;
    row[512 + j] = hi;
    row[1024 + j] = __float2bfloat16(lo);
}

__global__ void zero_state() {
    int i = blockIdx.x * 256 + threadIdx.x;
    g_hT[i] = 0.f;
    g_c[i] = 0.f;
}

// ---------------------------------------------------------------------------
__global__ void __launch_bounds__(512) attn_kernel(
    const float* __restrict__ enc, const float* __restrict__ vattn) {
    const int b = blockIdx.x, tid = threadIdx.x;
    __shared__ float hp_s[H_];
    __shared__ float v_s[H_];
    __shared__ float sc[64];

    hp_s[tid] = g_hp4[0 * B_ * H_ + b * H_ + tid]
              + g_hp4[1 * B_ * H_ + b * H_ + tid]
              + g_hp4[2 * B_ * H_ + b * H_ + tid]
              + g_hp4[3 * B_ * H_ + b * H_ + tid];
    v_s[tid] = vattn[tid];
    __syncthreads();

    const int w = tid >> 5, lane = tid & 31;
    const float* ep = g_enc_proj + (size_t)b * L_ * H_;
    for (int l = w; l < L_; l += 16) {
        const float* row = ep + l * H_;
        float p = 0.f;
#pragma unroll
        for (int k = lane; k < H_; k += 32)
            p += ftanh(hp_s[k] + row[k]) * v_s[k];
#pragma unroll
        for (int o = 16; o; o >>= 1) p += __shfl_xor_sync(0xffffffffu, p, o);
        if (lane == 0) sc[l] = p;
    }
    __syncthreads();

    if (tid < 32) {
        float v0 = sc[tid];
        float v1 = (tid < L_ - 32) ? sc[32 + tid] : -1e30f;
        float mx = fmaxf(v0, v1);
#pragma unroll
        for (int o = 16; o; o >>= 1) mx = fmaxf(mx, __shfl_xor_sync(0xffffffffu, mx, o));
        float e0 = fex2((v0 - mx) * 1.4426950408889634f);
        float e1 = (tid < L_ - 32) ? fex2((v1 - mx) * 1.4426950408889634f) : 0.f;
        float s = e0 + e1;
#pragma unroll
        for (int o = 16; o; o >>= 1) s += __shfl_xor_sync(0xffffffffu, s, o);
        float r = frcp(s);
        sc[tid] = e0 * r;
        if (tid < L_ - 32) sc[32 + tid] = e1 * r;
    }
    __syncthreads();

    const float* eb = enc + (size_t)b * L_ * ENC_;
    float a = 0.f;
#pragma unroll 7
    for (int l = 0; l < L_; l++) a += sc[l] * eb[l * ENC_ + tid];
    g_ctxT[(size_t)tid * B_ + b] = a;
}

// ---------------------------------------------------------------------------
__global__ void __launch_bounds__(512) lstm_pw(int t) {
    const int b = blockIdx.x, j = threadIdx.x;
    const float* gp = g_gates_pre + ((size_t)(t * B_ + b)) * (4 * H_);
    const float* g0 = g_gates2 + (size_t)b * (4 * H_);
    const float* g1 = g_gates2 + (size_t)B_ * (4 * H_) + (size_t)b * (4 * H_);
    float gi = g0[j]          + g1[j]          + gp[j];
    float gf = g0[H_ + j]     + g1[H_ + j]     + gp[H_ + j];
    float gg = g0[2 * H_ + j] + g1[2 * H_ + j] + gp[2 * H_ + j];
    float go = g0[3 * H_ + j] + g1[3 * H_ + j] + gp[3 * H_ + j];

    const float* cin = g_c + (size_t)(t & 1) * B_ * H_ + (size_t)b * H_;
    float* cout = g_c + (size_t)((t + 1) & 1) * B_ * H_ + (size_t)b * H_;
    float cn = fsig(gf) * cin[j] + fsig(gi) * ftanh(gg);
    cout[j] = cn;
    float h = fsig(go) * ftanh(cn);
    g_hT[(size_t)(t + 1) * H_ * B_ + (size_t)j * B_ + b] = h;

    // bf16 hi/lo A-panels for the HMMA logits GEMM of step t
    __nv_bfloat16 h1 = __float2bfloat16(h);
    float h2 = h - __bfloat162float(h1);
    __nv_bfloat16* row = g_hbig + ((size_t)t * B_ + b) * KBIG_;
    row[j]        = h1;
    row[512 + j]  = h1;
    row[1024 + j] = __float2bfloat16(h2);
}

// ---------------------------------------------------------------------------
extern "C" void kernel_launch(void* const* d_in, const int* in_sizes, int n_in,
                              void* d_out, int out_size) {
    const int*   captions = (const int*)d_in[0];
    const float* enc      = (const float*)d_in[1];
    const float* emb      = (const float*)d_in[2];
    const float* W_h      = (const float*)d_in[3];
    const float* W_e      = (const float*)d_in[4];
    const float* v_attn   = (const float*)d_in[5];
    const float* W_ih     = (const float*)d_in[6];
    const float* W_hh     = (const float*)d_in[7];
    const float* b_ih     = (const float*)d_in[8];
    const float* b_hh     = (const float*)d_in[9];
    const float* W_fc     = (const float*)d_in[10];
    const float* b_fc     = (const float*)d_in[11];
    float* out = (float*)d_out;

    static cudaStream_t s2 = nullptr, s3 = nullptr;
    static cudaEvent_t evStart = nullptr, evG = nullptr, evH = nullptr,
                       evJ2 = nullptr;
    if (!s2) {
        cudaStreamCreateWithFlags(&s2, cudaStreamNonBlocking);
        cudaStreamCreateWithFlags(&s3, cudaStreamNonBlocking);
        cudaEventCreateWithFlags(&evStart, cudaEventDisableTiming);
        cudaEventCreateWithFlags(&evG,  cudaEventDisableTiming);
        cudaEventCreateWithFlags(&evH,  cudaEventDisableTiming);
        cudaEventCreateWithFlags(&evJ2, cudaEventDisableTiming);
    }

    float *enc_proj, *gates_pre, *WgT2, *WhT, *bsum, *hp4, *ctxT, *hT, *gates2;
    __nv_bfloat16 *Wbig, *hbig, *encA, *embX, *WeB, *WihB;
    cudaGetSymbolAddress((void**)&enc_proj,  g_enc_proj);
    cudaGetSymbolAddress((void**)&gates_pre, g_gates_pre);
    cudaGetSymbolAddress((void**)&WgT2,      g_WgT2);
    cudaGetSymbolAddress((void**)&WhT,       g_WhT);
    cudaGetSymbolAddress((void**)&bsum,      g_bsum);
    cudaGetSymbolAddress((void**)&hp4,       g_hp4);
    cudaGetSymbolAddress((void**)&ctxT,      g_ctxT);
    cudaGetSymbolAddress((void**)&hT,        g_hT);
    cudaGetSymbolAddress((void**)&gates2,    g_gates2);
    cudaGetSymbolAddress((void**)&Wbig,      g_Wbig);
    cudaGetSymbolAddress((void**)&hbig,      g_hbig);
    cudaGetSymbolAddress((void**)&encA,      g_encA);
    cudaGetSymbolAddress((void**)&embX,      g_embX);
    cudaGetSymbolAddress((void**)&WeB,       g_WeB);
    cudaGetSymbolAddress((void**)&WihB,      g_WihB);

    const dim3 tb(32, 8);

    // fork: s2 and s3 join the capture BEFORE any of their work
    zero_state<<<256, 256>>>();
    cudaEventRecord(evStart, 0);
    cudaStreamWaitEvent(s2, evStart, 0);
    cudaStreamWaitEvent(s3, evStart, 0);

    // s2: W_fc split (feeds logits)
    bsplit<<<VPAD_, 512, 0, s2>>>(W_fc, H_, Wbig, V_);

    // s3: gates_pre pipeline (emb gather+split, W_ih slice split, bias, GEMM)
    bias_sum<<<8, 256, 0, s3>>>(b_ih, b_hh);
    emb_gather<<<BT_, 512, 0, s3>>>(captions, emb);
    bsplit<<<4 * H_, 512, 0, s3>>>(W_ih, 1024, WihB, 4 * H_);
    mma_gemm<<<dim3(16, T_), 256, 0, s3>>>(embX, WihB, bsum, gates_pre,
                                           4L * H_, 4 * H_);
    cudaEventRecord(evG, s3);

    // s1: transposes for in-loop f32x2 GEMMs, enc_proj
    transp<<<dim3(16, 16), tb>>>(W_h, WhT, H_, H_, H_, H_);
    transp<<<dim3(16, 64), tb>>>(W_ih + 512, WgT2, 4 * H_, 512, 1024, 4 * H_);
    transp<<<dim3(16, 64), tb>>>(W_hh, WgT2 + 512L * 4 * H_, 4 * H_, 512,
                                 512, 4 * H_);
    bsplit<<<H_, 512>>>(W_e, ENC_, WeB, H_);
    asplit<<<BL_, 512>>>(enc, encA);
    mma_gemm<<<dim3(4, BL_ / 128), 256>>>(encA, WeB, nullptr, enc_proj,
                                          (long)H_, H_);

    for (int t = 0; t < T_; t++) {
        const float* hTt = hT + (size_t)t * H_ * B_;
        {   // hidden projection, 4-way split-K
            XP x{{hTt, hTt + 128 * B_, hTt + 256 * B_, hTt + 384 * B_}};
            gemm_t<32><<<dim3(16, 1, 4), 256>>>(x, B_, WhT, H_, nullptr,
                                                hp4, (long)H_, (long)(B_ * H_),
                                                H_, 128);
        }
        attn_kernel<<<B_, 512>>>(enc, v_attn);
        {   // gates (ctx | h), 2-way split-K over [W_ih[:,512:] ; W_hh]
            XP x{{ctxT, hTt, ctxT, ctxT}};
            gemm_t<32><<<dim3(64, 1, 2), 256>>>(x, B_, WgT2, 4 * H_, nullptr,
                                                gates2, 4L * H_,
                                                (long)(B_ * 4 * H_), 4 * H_, H_);
        }
        if (t == 0) cudaStreamWaitEvent(0, evG, 0);   // join s3
        lstm_pw<<<B_, 512>>>(t);
        cudaEventRecord(evH, 0);
        cudaStreamWaitEvent(s2, evH, 0);
        // logits on s2 (HMMA), overlapped with next step's chain
        mma_gemm<<<dim3(VPAD_ / 128, 1), 256, 0, s2>>>(
            hbig + (size_t)t * B_ * KBIG_, Wbig, b_fc,
            out + (size_t)t * V_, (long)(T_ * V_), V_);
    }
    cudaEventRecord(evJ2, s2);                        // join s2
    cudaStreamWaitEvent(0, evJ2, 0);
}